// round 13
// baseline (speedup 1.0000x reference)
#include <cuda_runtime.h>
#include <math.h>
#include <stdint.h>

#define NNODE 512
#define MEMD  512
#define NIOU  1536
#define NCOMB 2048
#define NPAD  513

// Scratch state (device globals: allocation-free rule)
__device__ float g_xiouf[2 * NNODE * NCOMB];  // [xiou(1536) | xf(512)] per node, biases included
__device__ float g_zyA[2 * NPAD * NCOMB];     // K-slice 0 partial of h @ [W_iouh | W_fh]
__device__ float g_zyB[2 * NPAD * NCOMB];     // K-slice 1 partial
__device__ float g_c[2 * NPAD * MEMD];
__device__ float g_h[2 * NPAD * MEMD];
__device__ float g_part[16 * MEMD];           // head partial sums

__device__ __forceinline__ float sigm(float x) { return 1.f / (1.f + __expf(-x)); }
__device__ __forceinline__ float4 ld4(const float* p) { return *(const float4*)p; }
__device__ __forceinline__ float4 f4add(float4 a, float4 b) {
    return make_float4(a.x + b.x, a.y + b.y, a.z + b.z, a.w + b.w);
}
__device__ __forceinline__ uint32_t to_tf32(float x) {
    uint32_t r; asm("cvt.rna.tf32.f32 %0, %1;" : "=r"(r) : "f"(x)); return r;
}
__device__ __forceinline__ uint4 cvt4(float4 v) {
    uint4 r; r.x = to_tf32(v.x); r.y = to_tf32(v.y); r.z = to_tf32(v.z); r.w = to_tf32(v.w);
    return r;
}
__device__ __forceinline__ void mma_tf32(float d[4], const uint32_t a[4], const uint32_t b[2]) {
    asm volatile(
        "mma.sync.aligned.m16n8k8.row.col.f32.tf32.tf32.f32 "
        "{%0,%1,%2,%3}, {%4,%5,%6,%7}, {%8,%9}, {%0,%1,%2,%3};"
        : "+f"(d[0]), "+f"(d[1]), "+f"(d[2]), "+f"(d[3])
        : "r"(a[0]), "r"(a[1]), "r"(a[2]), "r"(a[3]), "r"(b[0]), "r"(b[1]));
}

// Precompute tf32 GEMM: 64(M)x64(N)xK512 block tile, BK=32, 128 threads (4 warps,
// 32x32 warp tiles => 2 LDS per MMA), double-buffered, conflict-free strides
// (As stride 36 = 4 mod 32 for the g*stride+tg A-frag pattern; Bs 72 = 8 mod 32).
// C[m] = emb[tok[m]] @ [W_ioux|W_fx] + [b_ioux|b_fx]  -> g_xiouf  (m over 1024 rows)
__global__ __launch_bounds__(128) void k_pre(
    const float* __restrict__ emb, const int* __restrict__ linp, const int* __restrict__ rinp,
    const float* __restrict__ W0, const float* __restrict__ W1,
    const float* __restrict__ b0, const float* __restrict__ b1)
{
    __shared__ uint32_t As[2][64][36];
    __shared__ uint32_t Bs[2][32][72];

    const int tid = threadIdx.x;
    const int n0 = blockIdx.x * 64;   // 32 n-strips (1536 boundary at strip 24, not straddled)
    const int m0 = blockIdx.y * 64;   // 16 m-tiles

    const int ar0 = tid >> 3;         // A row base, +16 per i
    const int ac  = (tid & 7) << 2;   // A col (float4)
    const int br0 = tid >> 4;         // B row base, +8 per i
    const int bc  = (tid & 15) << 2;  // B col (float4)

    const float* aptr[4];
#pragma unroll
    for (int i = 0; i < 4; i++) {
        int gm = m0 + ar0 + 16 * i;
        int tok = (gm < NNODE) ? linp[gm] : rinp[gm - NNODE];
        aptr[i] = emb + (size_t)tok * MEMD + ac;
    }

    const float* Bsrc; int bld; const float* bias;
    if (n0 < NIOU) { Bsrc = W0 + n0;          bld = NIOU; bias = b0 + n0; }
    else           { Bsrc = W1 + (n0 - NIOU); bld = MEMD; bias = b1 + n0 - NIOU; }

    const int lane = tid & 31, wid = tid >> 5;
    const int wm = (wid & 1) * 32, wn = (wid >> 1) * 32;
    const int g = lane >> 2, tg = lane & 3;

    float acc[2][4][4] = {};

#pragma unroll
    for (int i = 0; i < 4; i++) {
        *(uint4*)&As[0][ar0 + 16 * i][ac] = cvt4(ld4(aptr[i]));
        *(uint4*)&Bs[0][br0 + 8 * i][bc]  = cvt4(ld4(Bsrc + (size_t)(br0 + 8 * i) * bld + bc));
    }
    __syncthreads();

    int cur = 0;
    for (int it = 0; it < 16; it++) {
        float4 an[4], bn[4];
        if (it < 15) {
            int k0 = (it + 1) * 32;
#pragma unroll
            for (int i = 0; i < 4; i++) {
                an[i] = ld4(aptr[i] + k0);
                bn[i] = ld4(Bsrc + (size_t)(k0 + br0 + 8 * i) * bld + bc);
            }
        }
#pragma unroll
        for (int kk = 0; kk < 32; kk += 8) {
            uint32_t af[2][4], bf[4][2];
#pragma unroll
            for (int i = 0; i < 2; i++) {
                int r = wm + i * 16 + g;
                af[i][0] = As[cur][r][kk + tg];
                af[i][1] = As[cur][r + 8][kk + tg];
                af[i][2] = As[cur][r][kk + tg + 4];
                af[i][3] = As[cur][r + 8][kk + tg + 4];
            }
#pragma unroll
            for (int j = 0; j < 4; j++) {
                int c = wn + j * 8 + g;
                bf[j][0] = Bs[cur][kk + tg][c];
                bf[j][1] = Bs[cur][kk + tg + 4][c];
            }
#pragma unroll
            for (int i = 0; i < 2; i++)
#pragma unroll
                for (int j = 0; j < 4; j++)
                    mma_tf32(acc[i][j], af[i], bf[j]);
        }
        if (it < 15) {
            int nxt = cur ^ 1;
#pragma unroll
            for (int i = 0; i < 4; i++) {
                *(uint4*)&As[nxt][ar0 + 16 * i][ac] = cvt4(an[i]);
                *(uint4*)&Bs[nxt][br0 + 8 * i][bc]  = cvt4(bn[i]);
            }
            __syncthreads();
            cur = nxt;
        }
    }

#pragma unroll
    for (int i = 0; i < 2; i++)
#pragma unroll
        for (int j = 0; j < 4; j++) {
            int colin = wn + j * 8 + 2 * tg;
#pragma unroll
            for (int r = 0; r < 2; r++) {
                int mrow = m0 + wm + i * 16 + g + r * 8;
                float2 v = make_float2(acc[i][j][2 * r], acc[i][j][2 * r + 1]);
                v.x += bias[colin]; v.y += bias[colin + 1];
                *(float2*)(g_xiouf + (size_t)mrow * NCOMB + n0 + colin) = v;
            }
        }
}

// Level GEMM with split-K=2 + PDL prologue: B-weight tile 0 is staged into smem
// BEFORE cudaGridDependencySynchronize (weights are kernel inputs, independent of
// the predecessor). A (g_h, written by predecessor k_update) is loaded after.
// As stride 36 (= 4 mod 32): conflict-free A-frag reads.
__global__ __launch_bounds__(256) void k_lvl(
    const float* __restrict__ Wiouh, const float* __restrict__ Wfh, int j0, int P)
{
    __shared__ uint32_t As[2][32][36];
    __shared__ uint32_t Bs[2][32][72];

    const int tid = threadIdx.x;
    const int n0 = blockIdx.x * 64;
    const int mt = blockIdx.y >> 1;
    const int s  = blockIdx.y & 1;
    const int t  = blockIdx.z;
    const int kbase = s * 256;
    const int m0 = mt * 32;

    const int arow = tid >> 3;
    const int acol = (tid & 7) << 2;
    const int brow = tid >> 4;
    const int bc4  = (tid & 15) << 2;

    const float* Bsrc; int bld;
    if (n0 < NIOU) { Bsrc = Wiouh + n0;          bld = NIOU; }
    else           { Bsrc = Wfh + (n0 - NIOU);   bld = MEMD; }
    Bsrc += (size_t)kbase * bld;

    // ---- PDL prologue: weights only ----
    *(uint4*)&Bs[0][brow][bc4]      = cvt4(ld4(Bsrc + (size_t)brow * bld + bc4));
    *(uint4*)&Bs[0][brow + 16][bc4] = cvt4(ld4(Bsrc + (size_t)(brow + 16) * bld + bc4));

    cudaGridDependencySynchronize();

    const int gm = m0 + arow;
    const bool avalid = (gm < P);
    const float* aptr = g_h + (size_t)(t * NPAD + j0 + (avalid ? gm : 0)) * MEMD + kbase + acol;

    {
        float4 av = avalid ? ld4(aptr) : make_float4(0.f, 0.f, 0.f, 0.f);
        *(uint4*)&As[0][arow][acol] = cvt4(av);
    }

    const int lane = tid & 31, wid = tid >> 5;
    const int wm = (wid & 1) * 16, wn = (wid >> 1) * 16;
    const int g = lane >> 2, tg = lane & 3;

    float acc[2][4] = {};
    __syncthreads();

    int cur = 0;
    for (int it = 0; it < 8; it++) {
        float4 an, bn0, bn1;
        if (it < 7) {
            int k0 = (it + 1) * 32;
            an  = avalid ? ld4(aptr + k0) : make_float4(0.f, 0.f, 0.f, 0.f);
            bn0 = ld4(Bsrc + (size_t)(k0 + brow) * bld + bc4);
            bn1 = ld4(Bsrc + (size_t)(k0 + brow + 16) * bld + bc4);
        }
#pragma unroll
        for (int kk = 0; kk < 32; kk += 8) {
            uint32_t af[4], bf[2][2];
            af[0] = As[cur][wm + g][kk + tg];
            af[1] = As[cur][wm + g + 8][kk + tg];
            af[2] = As[cur][wm + g][kk + tg + 4];
            af[3] = As[cur][wm + g + 8][kk + tg + 4];
#pragma unroll
            for (int j = 0; j < 2; j++) {
                int bc = wn + j * 8 + g;
                bf[j][0] = Bs[cur][kk + tg][bc];
                bf[j][1] = Bs[cur][kk + tg + 4][bc];
            }
            mma_tf32(acc[0], af, bf[0]);
            mma_tf32(acc[1], af, bf[1]);
        }
        if (it < 7) {
            int nxt = cur ^ 1;
            *(uint4*)&As[nxt][arow][acol]     = cvt4(an);
            *(uint4*)&Bs[nxt][brow][bc4]      = cvt4(bn0);
            *(uint4*)&Bs[nxt][brow + 16][bc4] = cvt4(bn1);
            __syncthreads();
            cur = nxt;
        }
    }

    float* zout = s ? g_zyB : g_zyA;
#pragma unroll
    for (int j = 0; j < 2; j++) {
        int colin = wn + j * 8 + 2 * tg;
#pragma unroll
        for (int r = 0; r < 2; r++) {
            int mrow = m0 + wm + g + r * 8;
            if (mrow < P) {
                float2 v = make_float2(acc[j][2 * r], acc[j][2 * r + 1]);
                *(float2*)(zout + (size_t)(t * NPAD + j0 + mrow) * NCOMB + n0 + colin) = v;
            }
        }
    }
}

// Per-node gate math for one level (PDL: indices + biases loaded pre-sync).
__global__ __launch_bounds__(128) void k_update(
    const int* __restrict__ lch, const int* __restrict__ rch,
    const float* __restrict__ biouh, const float* __restrict__ bfh, int j0)
{
    const int t = blockIdx.y;
    const int j = j0 + blockIdx.x;
    const int* ch = (t ? rch : lch) + j * 4;
    const int d = threadIdx.x << 2;

    // ---- PDL prologue: kernel inputs only ----
    const int c0i = ch[0], c1i = ch[1], c2i = ch[2], c3i = ch[3];
    float4 Bi = ld4(biouh + d), Bo = ld4(biouh + 512 + d), Bu = ld4(biouh + 1024 + d), Bf = ld4(bfh + d);

    cudaGridDependencySynchronize();

    const int chl[4] = {c0i, c1i, c2i, c3i};
    const float* x = g_xiouf + (size_t)(t * NNODE + j) * NCOMB;

    float4 Zi = make_float4(0.f, 0.f, 0.f, 0.f);
    float4 Zo = Zi, Zu = Zi;
    float4 Y[4], Cc[4];
#pragma unroll
    for (int q = 0; q < 4; q++) {
        int c = chl[q];
        if (c < NNODE) {
            size_t zoff = (size_t)(t * NPAD + c) * NCOMB;
            const float* zA = g_zyA + zoff;
            const float* zB = g_zyB + zoff;
            Zi = f4add(Zi, f4add(ld4(zA + d),        ld4(zB + d)));
            Zo = f4add(Zo, f4add(ld4(zA + 512 + d),  ld4(zB + 512 + d)));
            Zu = f4add(Zu, f4add(ld4(zA + 1024 + d), ld4(zB + 1024 + d)));
            Y[q]  = f4add(ld4(zA + 1536 + d), ld4(zB + 1536 + d));
            Cc[q] = ld4(g_c + (size_t)(t * NPAD + c) * MEMD + d);
        } else {
            Y[q] = Cc[q] = make_float4(0.f, 0.f, 0.f, 0.f);
        }
    }

    float4 Xi = ld4(x + d), Xo = ld4(x + 512 + d), Xu = ld4(x + 1024 + d), Xf = ld4(x + 1536 + d);

    float4 Oc, Oh;
#define DO(C) { \
    float ig = sigm(Xi.C + Zi.C + Bi.C); \
    float og = sigm(Xo.C + Zo.C + Bo.C); \
    float ug = tanhf(Xu.C + Zu.C + Bu.C); \
    float fb = Xf.C + Bf.C; \
    float c  = ig * ug + sigm(Y[0].C + fb) * Cc[0].C + sigm(Y[1].C + fb) * Cc[1].C \
                       + sigm(Y[2].C + fb) * Cc[2].C + sigm(Y[3].C + fb) * Cc[3].C; \
    Oc.C = c; Oh.C = og * tanhf(c); }
    DO(x) DO(y) DO(z) DO(w)
#undef DO

    *(float4*)(g_c + (size_t)(t * NPAD + j) * MEMD + d) = Oc;
    *(float4*)(g_h + (size_t)(t * NPAD + j) * MEMD + d) = Oh;
}

// Fused root-update + head part 1. Each of 16 blocks recomputes the 64-dim slice
// of the root cell state it needs (redundant x2 across blocks; trivial cost),
// then forms vec = [lc*rc | |lc-rc|] slice and partial hid pre-activations.
__global__ __launch_bounds__(512) void k_head1f(
    const int* __restrict__ lch, const int* __restrict__ rch,
    const float* __restrict__ biouh, const float* __restrict__ bfh,
    const float* __restrict__ Wh)
{
    __shared__ float sh_c[2][64];
    __shared__ float vec_s[64];
    const int b = blockIdx.x, tid = threadIdx.x;
    const int s0 = (b & 7) * 64;

    cudaGridDependencySynchronize();

    if (tid < 128) {
        int t = tid >> 6;
        int i = tid & 63;
        int dd = s0 + i;
        const int* ch = (t ? rch : lch) + 511 * 4;
        const float* x = g_xiouf + (size_t)(t * NNODE + 511) * NCOMB;
        float zi = 0.f, zu = 0.f;
        float y[4], cc[4];
#pragma unroll
        for (int q = 0; q < 4; q++) {
            int c = ch[q];  // root children are real nodes
            size_t zoff = (size_t)(t * NPAD + c) * NCOMB;
            zi += g_zyA[zoff + dd] + g_zyB[zoff + dd];
            zu += g_zyA[zoff + 1024 + dd] + g_zyB[zoff + 1024 + dd];
            y[q]  = g_zyA[zoff + 1536 + dd] + g_zyB[zoff + 1536 + dd];
            cc[q] = g_c[(size_t)(t * NPAD + c) * MEMD + dd];
        }
        float ig = sigm(x[dd] + zi + biouh[dd]);
        float ug = tanhf(x[1024 + dd] + zu + biouh[1024 + dd]);
        float fb = x[1536 + dd] + bfh[dd];
        float cval = ig * ug + sigm(y[0] + fb) * cc[0] + sigm(y[1] + fb) * cc[1]
                             + sigm(y[2] + fb) * cc[2] + sigm(y[3] + fb) * cc[3];
        sh_c[t][i] = cval;
    }
    __syncthreads();
    if (tid < 64) {
        float l = sh_c[0][tid], r = sh_c[1][tid];
        vec_s[tid] = (b < 8) ? l * r : fabsf(l - r);
    }
    __syncthreads();
    float acc = 0.f;
    int d0 = b * 64;
#pragma unroll 8
    for (int dd = 0; dd < 64; dd++)
        acc += vec_s[dd] * Wh[(size_t)(d0 + dd) * 512 + tid];
    g_part[b * 512 + tid] = acc;
}

// Head part 2: hid = sigmoid(.+bh); logits = hid@Wp+bp; log_softmax -> out[5]
__global__ __launch_bounds__(512) void k_head2(
    const float* __restrict__ bh, const float* __restrict__ Wp,
    const float* __restrict__ bp, float* __restrict__ out)
{
    __shared__ float hid[512];
    __shared__ float logit[5];
    const int tid = threadIdx.x;

    cudaGridDependencySynchronize();

    float a = 0.f;
#pragma unroll
    for (int b = 0; b < 16; b++) a += g_part[b * 512 + tid];
    hid[tid] = sigm(a + bh[tid]);
    __syncthreads();
    if (tid < 160) {
        int c = tid / 32, lane = tid & 31;
        float s = 0.f;
        for (int o = lane; o < 512; o += 32) s += hid[o] * Wp[o * 5 + c];
#pragma unroll
        for (int off = 16; off; off >>= 1) s += __shfl_down_sync(0xffffffffu, s, off);
        if (lane == 0) logit[c] = s + bp[c];
    }
    __syncthreads();
    if (tid == 0) {
        float m = logit[0];
#pragma unroll
        for (int c = 1; c < 5; c++) m = fmaxf(m, logit[c]);
        float se = 0.f;
#pragma unroll
        for (int c = 0; c < 5; c++) se += expf(logit[c] - m);
        float lse = m + logf(se);
#pragma unroll
        for (int c = 0; c < 5; c++) out[c] = logit[c] - lse;
    }
}

extern "C" void kernel_launch(void* const* d_in, const int* in_sizes, int n_in,
                              void* d_out, int out_size)
{
    const int*   linp  = (const int*)d_in[0];
    const int*   rinp  = (const int*)d_in[1];
    const int*   lch   = (const int*)d_in[2];
    const int*   rch   = (const int*)d_in[3];
    const float* emb   = (const float*)d_in[4];
    const float* Wioux = (const float*)d_in[5];
    const float* bioux = (const float*)d_in[6];
    const float* Wiouh = (const float*)d_in[7];
    const float* biouh = (const float*)d_in[8];
    const float* Wfx   = (const float*)d_in[9];
    const float* bfx   = (const float*)d_in[10];
    const float* Wfh   = (const float*)d_in[11];
    const float* bfh   = (const float*)d_in[12];
    const float* Wh    = (const float*)d_in[13];
    const float* bh    = (const float*)d_in[14];
    const float* Wp    = (const float*)d_in[15];
    const float* bp    = (const float*)d_in[16];
    float* out = (float*)d_out;

    // First launch: normal (its predecessor is outside our chain).
    k_pre<<<dim3(32, 16, 1), 128>>>(emb, linp, rinp, Wioux, Wfx, bioux, bfx);

    // All subsequent launches: PDL so each kernel's launch + input-only prologue
    // overlaps the predecessor's tail.
    cudaLaunchAttribute attr;
    attr.id = cudaLaunchAttributeProgrammaticStreamSerialization;
    attr.val.programmaticStreamSerializationAllowed = 1;
    cudaLaunchConfig_t cfg = {};
    cfg.attrs = &attr;
    cfg.numAttrs = 1;
    cfg.stream = 0;

    static const int j0s[5] = {0, 171, 427, 491, 507};
    static const int cnt[5] = {171, 256, 64, 16, 4};
    for (int l = 0; l < 5; l++) {
        cfg.gridDim = dim3(cnt[l], 2, 1);
        cfg.blockDim = dim3(128, 1, 1);
        cudaLaunchKernelEx(&cfg, k_update, lch, rch, biouh, bfh, j0s[l]);

        int mt = (cnt[l] + 31) / 32;
        cfg.gridDim = dim3(32, mt * 2, 2);
        cfg.blockDim = dim3(256, 1, 1);
        cudaLaunchKernelEx(&cfg, k_lvl, Wiouh, Wfh, j0s[l], cnt[l]);
    }

    cfg.gridDim = dim3(16, 1, 1);
    cfg.blockDim = dim3(512, 1, 1);
    cudaLaunchKernelEx(&cfg, k_head1f, lch, rch, biouh, bfh, Wh);

    cfg.gridDim = dim3(1, 1, 1);
    cfg.blockDim = dim3(512, 1, 1);
    cudaLaunchKernelEx(&cfg, k_head2, bh, Wp, bp, out);
}

// round 14
// speedup vs baseline: 1.3933x; 1.3933x over previous
#include <cuda_runtime.h>
#include <math.h>
#include <stdint.h>

#define NNODE 512
#define MEMD  512
#define NIOU  1536
#define NCOMB 2048
#define NPAD  513

// Scratch state (device globals: allocation-free rule)
__device__ float g_xiouf[2 * NNODE * NCOMB];  // [xiou(1536) | xf(512)] per node, biases included
__device__ float g_zyA[2 * NPAD * NCOMB];     // K-slice 0 partial of h @ [W_iouh | W_fh]
__device__ float g_zyB[2 * NPAD * NCOMB];     // K-slice 1 partial
__device__ float g_c[2 * NPAD * MEMD];
__device__ float g_h[2 * NPAD * MEMD];
__device__ float g_part[16 * MEMD];           // head partial sums

__device__ __forceinline__ float sigm(float x) { return 1.f / (1.f + __expf(-x)); }
__device__ __forceinline__ float4 ld4(const float* p) { return *(const float4*)p; }
__device__ __forceinline__ float4 f4add(float4 a, float4 b) {
    return make_float4(a.x + b.x, a.y + b.y, a.z + b.z, a.w + b.w);
}
__device__ __forceinline__ uint32_t to_tf32(float x) {
    uint32_t r; asm("cvt.rna.tf32.f32 %0, %1;" : "=r"(r) : "f"(x)); return r;
}
__device__ __forceinline__ uint4 cvt4(float4 v) {
    uint4 r; r.x = to_tf32(v.x); r.y = to_tf32(v.y); r.z = to_tf32(v.z); r.w = to_tf32(v.w);
    return r;
}
__device__ __forceinline__ void mma_tf32(float d[4], const uint32_t a[4], const uint32_t b[2]) {
    asm volatile(
        "mma.sync.aligned.m16n8k8.row.col.f32.tf32.tf32.f32 "
        "{%0,%1,%2,%3}, {%4,%5,%6,%7}, {%8,%9}, {%0,%1,%2,%3};"
        : "+f"(d[0]), "+f"(d[1]), "+f"(d[2]), "+f"(d[3])
        : "r"(a[0]), "r"(a[1]), "r"(a[2]), "r"(a[3]), "r"(b[0]), "r"(b[1]));
}

// Precompute tf32 GEMM: 32(M)x64(N)xK512 block tile, BK=32, 256 threads (8 warps,
// 16x16 warp tiles), double-buffered smem. As stride 36 (= 4 mod 32): the A-frag
// pattern g*stride+tg is a lane-bijection -> conflict-free. Bs stride 72 (= 8 mod 32)
// for the tg*stride+g B-frag pattern.
// C[m] = emb[tok[m]] @ [W_ioux|W_fx] + [b_ioux|b_fx]  -> g_xiouf  (m over 1024 rows)
__global__ __launch_bounds__(256) void k_pre(
    const float* __restrict__ emb, const int* __restrict__ linp, const int* __restrict__ rinp,
    const float* __restrict__ W0, const float* __restrict__ W1,
    const float* __restrict__ b0, const float* __restrict__ b1)
{
    __shared__ uint32_t As[2][32][36];
    __shared__ uint32_t Bs[2][32][72];

    const int tid = threadIdx.x;
    const int n0 = blockIdx.x * 64;
    const int m0 = blockIdx.y * 32;

    const int arow = tid >> 3;
    const int acol = (tid & 7) << 2;
    const int brow = tid >> 4;
    const int bc4  = (tid & 15) << 2;

    const float* aptr;
    {
        int gm = m0 + arow;
        int tok = (gm < NNODE) ? linp[gm] : rinp[gm - NNODE];
        aptr = emb + (size_t)tok * MEMD + acol;
    }

    const float* Bsrc; int bld; const float* bias;
    if (n0 < NIOU) { Bsrc = W0 + n0;          bld = NIOU; bias = b0 + n0; }
    else           { Bsrc = W1 + (n0 - NIOU); bld = MEMD; bias = b1 + n0 - NIOU; }

    const int lane = tid & 31, wid = tid >> 5;
    const int wm = (wid & 1) * 16, wn = (wid >> 1) * 16;
    const int g = lane >> 2, tg = lane & 3;

    float acc[2][4] = {};

    *(uint4*)&As[0][arow][acol]     = cvt4(ld4(aptr));
    *(uint4*)&Bs[0][brow][bc4]      = cvt4(ld4(Bsrc + (size_t)brow * bld + bc4));
    *(uint4*)&Bs[0][brow + 16][bc4] = cvt4(ld4(Bsrc + (size_t)(brow + 16) * bld + bc4));
    __syncthreads();

    int cur = 0;
    for (int it = 0; it < 16; it++) {
        float4 an, bn0, bn1;
        if (it < 15) {
            int k0 = (it + 1) * 32;
            an  = ld4(aptr + k0);
            bn0 = ld4(Bsrc + (size_t)(k0 + brow) * bld + bc4);
            bn1 = ld4(Bsrc + (size_t)(k0 + brow + 16) * bld + bc4);
        }
#pragma unroll
        for (int kk = 0; kk < 32; kk += 8) {
            uint32_t af[4], bf[2][2];
            af[0] = As[cur][wm + g][kk + tg];
            af[1] = As[cur][wm + g + 8][kk + tg];
            af[2] = As[cur][wm + g][kk + tg + 4];
            af[3] = As[cur][wm + g + 8][kk + tg + 4];
#pragma unroll
            for (int j = 0; j < 2; j++) {
                int bc = wn + j * 8 + g;
                bf[j][0] = Bs[cur][kk + tg][bc];
                bf[j][1] = Bs[cur][kk + tg + 4][bc];
            }
            mma_tf32(acc[0], af, bf[0]);
            mma_tf32(acc[1], af, bf[1]);
        }
        if (it < 15) {
            int nxt = cur ^ 1;
            *(uint4*)&As[nxt][arow][acol]     = cvt4(an);
            *(uint4*)&Bs[nxt][brow][bc4]      = cvt4(bn0);
            *(uint4*)&Bs[nxt][brow + 16][bc4] = cvt4(bn1);
            __syncthreads();
            cur = nxt;
        }
    }

#pragma unroll
    for (int j = 0; j < 2; j++) {
        int colin = wn + j * 8 + 2 * tg;
#pragma unroll
        for (int r = 0; r < 2; r++) {
            int mrow = m0 + wm + g + r * 8;
            float2 v = make_float2(acc[j][2 * r], acc[j][2 * r + 1]);
            v.x += bias[colin]; v.y += bias[colin + 1];
            *(float2*)(g_xiouf + (size_t)mrow * NCOMB + n0 + colin) = v;
        }
    }
}

// Level GEMM with split-K=2 + PDL prologue: B-weight tile 0 is staged into smem
// BEFORE cudaGridDependencySynchronize (weights are kernel inputs, independent of
// the predecessor). A (g_h, written by predecessor k_update) is loaded after.
// As stride 36 (= 4 mod 32): conflict-free A-frag reads.
__global__ __launch_bounds__(256) void k_lvl(
    const float* __restrict__ Wiouh, const float* __restrict__ Wfh, int j0, int P)
{
    __shared__ uint32_t As[2][32][36];
    __shared__ uint32_t Bs[2][32][72];

    const int tid = threadIdx.x;
    const int n0 = blockIdx.x * 64;
    const int mt = blockIdx.y >> 1;
    const int s  = blockIdx.y & 1;
    const int t  = blockIdx.z;
    const int kbase = s * 256;
    const int m0 = mt * 32;

    const int arow = tid >> 3;
    const int acol = (tid & 7) << 2;
    const int brow = tid >> 4;
    const int bc4  = (tid & 15) << 2;

    const float* Bsrc; int bld;
    if (n0 < NIOU) { Bsrc = Wiouh + n0;          bld = NIOU; }
    else           { Bsrc = Wfh + (n0 - NIOU);   bld = MEMD; }
    Bsrc += (size_t)kbase * bld;

    // ---- PDL prologue: weights only ----
    *(uint4*)&Bs[0][brow][bc4]      = cvt4(ld4(Bsrc + (size_t)brow * bld + bc4));
    *(uint4*)&Bs[0][brow + 16][bc4] = cvt4(ld4(Bsrc + (size_t)(brow + 16) * bld + bc4));

    cudaGridDependencySynchronize();

    const int gm = m0 + arow;
    const bool avalid = (gm < P);
    const float* aptr = g_h + (size_t)(t * NPAD + j0 + (avalid ? gm : 0)) * MEMD + kbase + acol;

    {
        float4 av = avalid ? ld4(aptr) : make_float4(0.f, 0.f, 0.f, 0.f);
        *(uint4*)&As[0][arow][acol] = cvt4(av);
    }

    const int lane = tid & 31, wid = tid >> 5;
    const int wm = (wid & 1) * 16, wn = (wid >> 1) * 16;
    const int g = lane >> 2, tg = lane & 3;

    float acc[2][4] = {};
    __syncthreads();

    int cur = 0;
    for (int it = 0; it < 8; it++) {
        float4 an, bn0, bn1;
        if (it < 7) {
            int k0 = (it + 1) * 32;
            an  = avalid ? ld4(aptr + k0) : make_float4(0.f, 0.f, 0.f, 0.f);
            bn0 = ld4(Bsrc + (size_t)(k0 + brow) * bld + bc4);
            bn1 = ld4(Bsrc + (size_t)(k0 + brow + 16) * bld + bc4);
        }
#pragma unroll
        for (int kk = 0; kk < 32; kk += 8) {
            uint32_t af[4], bf[2][2];
            af[0] = As[cur][wm + g][kk + tg];
            af[1] = As[cur][wm + g + 8][kk + tg];
            af[2] = As[cur][wm + g][kk + tg + 4];
            af[3] = As[cur][wm + g + 8][kk + tg + 4];
#pragma unroll
            for (int j = 0; j < 2; j++) {
                int bc = wn + j * 8 + g;
                bf[j][0] = Bs[cur][kk + tg][bc];
                bf[j][1] = Bs[cur][kk + tg + 4][bc];
            }
            mma_tf32(acc[0], af, bf[0]);
            mma_tf32(acc[1], af, bf[1]);
        }
        if (it < 7) {
            int nxt = cur ^ 1;
            *(uint4*)&As[nxt][arow][acol]     = cvt4(an);
            *(uint4*)&Bs[nxt][brow][bc4]      = cvt4(bn0);
            *(uint4*)&Bs[nxt][brow + 16][bc4] = cvt4(bn1);
            __syncthreads();
            cur = nxt;
        }
    }

    float* zout = s ? g_zyB : g_zyA;
#pragma unroll
    for (int j = 0; j < 2; j++) {
        int colin = wn + j * 8 + 2 * tg;
#pragma unroll
        for (int r = 0; r < 2; r++) {
            int mrow = m0 + wm + g + r * 8;
            if (mrow < P) {
                float2 v = make_float2(acc[j][2 * r], acc[j][2 * r + 1]);
                *(float2*)(zout + (size_t)(t * NPAD + j0 + mrow) * NCOMB + n0 + colin) = v;
            }
        }
    }
}

// Per-node gate math for one level (PDL: indices + biases loaded pre-sync).
__global__ __launch_bounds__(128) void k_update(
    const int* __restrict__ lch, const int* __restrict__ rch,
    const float* __restrict__ biouh, const float* __restrict__ bfh, int j0)
{
    const int t = blockIdx.y;
    const int j = j0 + blockIdx.x;
    const int* ch = (t ? rch : lch) + j * 4;
    const int d = threadIdx.x << 2;

    // ---- PDL prologue: kernel inputs only ----
    const int c0i = ch[0], c1i = ch[1], c2i = ch[2], c3i = ch[3];
    float4 Bi = ld4(biouh + d), Bo = ld4(biouh + 512 + d), Bu = ld4(biouh + 1024 + d), Bf = ld4(bfh + d);

    cudaGridDependencySynchronize();

    const int chl[4] = {c0i, c1i, c2i, c3i};
    const float* x = g_xiouf + (size_t)(t * NNODE + j) * NCOMB;

    float4 Zi = make_float4(0.f, 0.f, 0.f, 0.f);
    float4 Zo = Zi, Zu = Zi;
    float4 Y[4], Cc[4];
#pragma unroll
    for (int q = 0; q < 4; q++) {
        int c = chl[q];
        if (c < NNODE) {
            size_t zoff = (size_t)(t * NPAD + c) * NCOMB;
            const float* zA = g_zyA + zoff;
            const float* zB = g_zyB + zoff;
            Zi = f4add(Zi, f4add(ld4(zA + d),        ld4(zB + d)));
            Zo = f4add(Zo, f4add(ld4(zA + 512 + d),  ld4(zB + 512 + d)));
            Zu = f4add(Zu, f4add(ld4(zA + 1024 + d), ld4(zB + 1024 + d)));
            Y[q]  = f4add(ld4(zA + 1536 + d), ld4(zB + 1536 + d));
            Cc[q] = ld4(g_c + (size_t)(t * NPAD + c) * MEMD + d);
        } else {
            Y[q] = Cc[q] = make_float4(0.f, 0.f, 0.f, 0.f);
        }
    }

    float4 Xi = ld4(x + d), Xo = ld4(x + 512 + d), Xu = ld4(x + 1024 + d), Xf = ld4(x + 1536 + d);

    float4 Oc, Oh;
#define DO(C) { \
    float ig = sigm(Xi.C + Zi.C + Bi.C); \
    float og = sigm(Xo.C + Zo.C + Bo.C); \
    float ug = tanhf(Xu.C + Zu.C + Bu.C); \
    float fb = Xf.C + Bf.C; \
    float c  = ig * ug + sigm(Y[0].C + fb) * Cc[0].C + sigm(Y[1].C + fb) * Cc[1].C \
                       + sigm(Y[2].C + fb) * Cc[2].C + sigm(Y[3].C + fb) * Cc[3].C; \
    Oc.C = c; Oh.C = og * tanhf(c); }
    DO(x) DO(y) DO(z) DO(w)
#undef DO

    *(float4*)(g_c + (size_t)(t * NPAD + j) * MEMD + d) = Oc;
    *(float4*)(g_h + (size_t)(t * NPAD + j) * MEMD + d) = Oh;
}

// Fused root-update + head part 1. Each of 16 blocks recomputes the 64-dim slice
// of the root cell state it needs (redundant x2 across blocks; trivial cost),
// then forms vec = [lc*rc | |lc-rc|] slice and partial hid pre-activations.
__global__ __launch_bounds__(512) void k_head1f(
    const int* __restrict__ lch, const int* __restrict__ rch,
    const float* __restrict__ biouh, const float* __restrict__ bfh,
    const float* __restrict__ Wh)
{
    __shared__ float sh_c[2][64];
    __shared__ float vec_s[64];
    const int b = blockIdx.x, tid = threadIdx.x;
    const int s0 = (b & 7) * 64;

    cudaGridDependencySynchronize();

    if (tid < 128) {
        int t = tid >> 6;
        int i = tid & 63;
        int dd = s0 + i;
        const int* ch = (t ? rch : lch) + 511 * 4;
        const float* x = g_xiouf + (size_t)(t * NNODE + 511) * NCOMB;
        float zi = 0.f, zu = 0.f;
        float y[4], cc[4];
#pragma unroll
        for (int q = 0; q < 4; q++) {
            int c = ch[q];  // root children are real nodes
            size_t zoff = (size_t)(t * NPAD + c) * NCOMB;
            zi += g_zyA[zoff + dd] + g_zyB[zoff + dd];
            zu += g_zyA[zoff + 1024 + dd] + g_zyB[zoff + 1024 + dd];
            y[q]  = g_zyA[zoff + 1536 + dd] + g_zyB[zoff + 1536 + dd];
            cc[q] = g_c[(size_t)(t * NPAD + c) * MEMD + dd];
        }
        float ig = sigm(x[dd] + zi + biouh[dd]);
        float ug = tanhf(x[1024 + dd] + zu + biouh[1024 + dd]);
        float fb = x[1536 + dd] + bfh[dd];
        float cval = ig * ug + sigm(y[0] + fb) * cc[0] + sigm(y[1] + fb) * cc[1]
                             + sigm(y[2] + fb) * cc[2] + sigm(y[3] + fb) * cc[3];
        sh_c[t][i] = cval;
    }
    __syncthreads();
    if (tid < 64) {
        float l = sh_c[0][tid], r = sh_c[1][tid];
        vec_s[tid] = (b < 8) ? l * r : fabsf(l - r);
    }
    __syncthreads();
    float acc = 0.f;
    int d0 = b * 64;
#pragma unroll 8
    for (int dd = 0; dd < 64; dd++)
        acc += vec_s[dd] * Wh[(size_t)(d0 + dd) * 512 + tid];
    g_part[b * 512 + tid] = acc;
}

// Head part 2: hid = sigmoid(.+bh); logits = hid@Wp+bp; log_softmax -> out[5]
__global__ __launch_bounds__(512) void k_head2(
    const float* __restrict__ bh, const float* __restrict__ Wp,
    const float* __restrict__ bp, float* __restrict__ out)
{
    __shared__ float hid[512];
    __shared__ float logit[5];
    const int tid = threadIdx.x;

    cudaGridDependencySynchronize();

    float a = 0.f;
#pragma unroll
    for (int b = 0; b < 16; b++) a += g_part[b * 512 + tid];
    hid[tid] = sigm(a + bh[tid]);
    __syncthreads();
    if (tid < 160) {
        int c = tid / 32, lane = tid & 31;
        float s = 0.f;
        for (int o = lane; o < 512; o += 32) s += hid[o] * Wp[o * 5 + c];
#pragma unroll
        for (int off = 16; off; off >>= 1) s += __shfl_down_sync(0xffffffffu, s, off);
        if (lane == 0) logit[c] = s + bp[c];
    }
    __syncthreads();
    if (tid == 0) {
        float m = logit[0];
#pragma unroll
        for (int c = 1; c < 5; c++) m = fmaxf(m, logit[c]);
        float se = 0.f;
#pragma unroll
        for (int c = 0; c < 5; c++) se += expf(logit[c] - m);
        float lse = m + logf(se);
#pragma unroll
        for (int c = 0; c < 5; c++) out[c] = logit[c] - lse;
    }
}

extern "C" void kernel_launch(void* const* d_in, const int* in_sizes, int n_in,
                              void* d_out, int out_size)
{
    const int*   linp  = (const int*)d_in[0];
    const int*   rinp  = (const int*)d_in[1];
    const int*   lch   = (const int*)d_in[2];
    const int*   rch   = (const int*)d_in[3];
    const float* emb   = (const float*)d_in[4];
    const float* Wioux = (const float*)d_in[5];
    const float* bioux = (const float*)d_in[6];
    const float* Wiouh = (const float*)d_in[7];
    const float* biouh = (const float*)d_in[8];
    const float* Wfx   = (const float*)d_in[9];
    const float* bfx   = (const float*)d_in[10];
    const float* Wfh   = (const float*)d_in[11];
    const float* bfh   = (const float*)d_in[12];
    const float* Wh    = (const float*)d_in[13];
    const float* bh    = (const float*)d_in[14];
    const float* Wp    = (const float*)d_in[15];
    const float* bp    = (const float*)d_in[16];
    float* out = (float*)d_out;

    // First launch: normal (its predecessor is outside our chain).
    k_pre<<<dim3(32, 32, 1), 256>>>(emb, linp, rinp, Wioux, Wfx, bioux, bfx);

    // All subsequent launches: PDL so each kernel's launch + input-only prologue
    // overlaps the predecessor's tail.
    cudaLaunchAttribute attr;
    attr.id = cudaLaunchAttributeProgrammaticStreamSerialization;
    attr.val.programmaticStreamSerializationAllowed = 1;
    cudaLaunchConfig_t cfg = {};
    cfg.attrs = &attr;
    cfg.numAttrs = 1;
    cfg.stream = 0;

    static const int j0s[5] = {0, 171, 427, 491, 507};
    static const int cnt[5] = {171, 256, 64, 16, 4};
    for (int l = 0; l < 5; l++) {
        cfg.gridDim = dim3(cnt[l], 2, 1);
        cfg.blockDim = dim3(128, 1, 1);
        cudaLaunchKernelEx(&cfg, k_update, lch, rch, biouh, bfh, j0s[l]);

        int mt = (cnt[l] + 31) / 32;
        cfg.gridDim = dim3(32, mt * 2, 2);
        cfg.blockDim = dim3(256, 1, 1);
        cudaLaunchKernelEx(&cfg, k_lvl, Wiouh, Wfh, j0s[l], cnt[l]);
    }

    cfg.gridDim = dim3(16, 1, 1);
    cfg.blockDim = dim3(512, 1, 1);
    cudaLaunchKernelEx(&cfg, k_head1f, lch, rch, biouh, bfh, Wh);

    cfg.gridDim = dim3(1, 1, 1);
    cfg.blockDim = dim3(512, 1, 1);
    cudaLaunchKernelEx(&cfg, k_head2, bh, Wp, bp, out);
}

// round 16
// speedup vs baseline: 1.4451x; 1.0372x over previous
#include <cuda_runtime.h>
#include <math.h>
#include <stdint.h>

#define NNODE 512
#define MEMD  512
#define NIOU  1536
#define NCOMB 2048
#define NPAD  513

// k_lvl dynamic smem: Bs[8][32][72] + As[2][32][36]
#define LVL_SMEM ((8 * 32 * 72 + 2 * 32 * 36) * 4)

// Scratch state (device globals: allocation-free rule)
__device__ float g_xiouf[2 * NNODE * NCOMB];  // [xiou(1536) | xf(512)] per node, biases included
__device__ float g_zyA[2 * NPAD * NCOMB];     // K-slice 0 partial of h @ [W_iouh | W_fh]
__device__ float g_zyB[2 * NPAD * NCOMB];     // K-slice 1 partial
__device__ float g_c[2 * NPAD * MEMD];
__device__ float g_h[2 * NPAD * MEMD];
__device__ float g_part[16 * MEMD];           // head partial sums

__device__ __forceinline__ float sigm(float x) { return 1.f / (1.f + __expf(-x)); }
__device__ __forceinline__ float4 ld4(const float* p) { return *(const float4*)p; }
__device__ __forceinline__ float4 f4add(float4 a, float4 b) {
    return make_float4(a.x + b.x, a.y + b.y, a.z + b.z, a.w + b.w);
}
__device__ __forceinline__ uint32_t to_tf32(float x) {
    uint32_t r; asm("cvt.rna.tf32.f32 %0, %1;" : "=r"(r) : "f"(x)); return r;
}
__device__ __forceinline__ uint4 cvt4(float4 v) {
    uint4 r; r.x = to_tf32(v.x); r.y = to_tf32(v.y); r.z = to_tf32(v.z); r.w = to_tf32(v.w);
    return r;
}
__device__ __forceinline__ void mma_tf32(float d[4], const uint32_t a[4], const uint32_t b[2]) {
    asm volatile(
        "mma.sync.aligned.m16n8k8.row.col.f32.tf32.tf32.f32 "
        "{%0,%1,%2,%3}, {%4,%5,%6,%7}, {%8,%9}, {%0,%1,%2,%3};"
        : "+f"(d[0]), "+f"(d[1]), "+f"(d[2]), "+f"(d[3])
        : "r"(a[0]), "r"(a[1]), "r"(a[2]), "r"(a[3]), "r"(b[0]), "r"(b[1]));
}

// Precompute tf32 GEMM: 32(M)x64(N)xK512 block tile, BK=32, 256 threads (8 warps,
// 16x16 warp tiles), double-buffered smem. As stride 36 (= 4 mod 32): conflict-free
// A-frag reads. Bs stride 72 (= 8 mod 32) for the B-frag pattern.
// C[m] = emb[tok[m]] @ [W_ioux|W_fx] + [b_ioux|b_fx]  -> g_xiouf  (m over 1024 rows)
__global__ __launch_bounds__(256) void k_pre(
    const float* __restrict__ emb, const int* __restrict__ linp, const int* __restrict__ rinp,
    const float* __restrict__ W0, const float* __restrict__ W1,
    const float* __restrict__ b0, const float* __restrict__ b1)
{
    __shared__ uint32_t As[2][32][36];
    __shared__ uint32_t Bs[2][32][72];

    const int tid = threadIdx.x;
    const int n0 = blockIdx.x * 64;
    const int m0 = blockIdx.y * 32;

    const int arow = tid >> 3;
    const int acol = (tid & 7) << 2;
    const int brow = tid >> 4;
    const int bc4  = (tid & 15) << 2;

    const float* aptr;
    {
        int gm = m0 + arow;
        int tok = (gm < NNODE) ? linp[gm] : rinp[gm - NNODE];
        aptr = emb + (size_t)tok * MEMD + acol;
    }

    const float* Bsrc; int bld; const float* bias;
    if (n0 < NIOU) { Bsrc = W0 + n0;          bld = NIOU; bias = b0 + n0; }
    else           { Bsrc = W1 + (n0 - NIOU); bld = MEMD; bias = b1 + n0 - NIOU; }

    const int lane = tid & 31, wid = tid >> 5;
    const int wm = (wid & 1) * 16, wn = (wid >> 1) * 16;
    const int g = lane >> 2, tg = lane & 3;

    float acc[2][4] = {};

    *(uint4*)&As[0][arow][acol]     = cvt4(ld4(aptr));
    *(uint4*)&Bs[0][brow][bc4]      = cvt4(ld4(Bsrc + (size_t)brow * bld + bc4));
    *(uint4*)&Bs[0][brow + 16][bc4] = cvt4(ld4(Bsrc + (size_t)(brow + 16) * bld + bc4));
    __syncthreads();

    int cur = 0;
    for (int it = 0; it < 16; it++) {
        float4 an, bn0, bn1;
        if (it < 15) {
            int k0 = (it + 1) * 32;
            an  = ld4(aptr + k0);
            bn0 = ld4(Bsrc + (size_t)(k0 + brow) * bld + bc4);
            bn1 = ld4(Bsrc + (size_t)(k0 + brow + 16) * bld + bc4);
        }
#pragma unroll
        for (int kk = 0; kk < 32; kk += 8) {
            uint32_t af[4], bf[2][2];
            af[0] = As[cur][wm + g][kk + tg];
            af[1] = As[cur][wm + g + 8][kk + tg];
            af[2] = As[cur][wm + g][kk + tg + 4];
            af[3] = As[cur][wm + g + 8][kk + tg + 4];
#pragma unroll
            for (int j = 0; j < 2; j++) {
                int bc = wn + j * 8 + g;
                bf[j][0] = Bs[cur][kk + tg][bc];
                bf[j][1] = Bs[cur][kk + tg + 4][bc];
            }
            mma_tf32(acc[0], af, bf[0]);
            mma_tf32(acc[1], af, bf[1]);
        }
        if (it < 15) {
            int nxt = cur ^ 1;
            *(uint4*)&As[nxt][arow][acol]     = cvt4(an);
            *(uint4*)&Bs[nxt][brow][bc4]      = cvt4(bn0);
            *(uint4*)&Bs[nxt][brow + 16][bc4] = cvt4(bn1);
            __syncthreads();
            cur = nxt;
        }
    }

#pragma unroll
    for (int j = 0; j < 2; j++) {
        int colin = wn + j * 8 + 2 * tg;
#pragma unroll
        for (int r = 0; r < 2; r++) {
            int mrow = m0 + wm + g + r * 8;
            float2 v = make_float2(acc[j][2 * r], acc[j][2 * r + 1]);
            v.x += bias[colin]; v.y += bias[colin + 1];
            *(float2*)(g_xiouf + (size_t)mrow * NCOMB + n0 + colin) = v;
        }
    }
}

// Level GEMM, split-K=2, full-B PDL prologue: ALL 8 B k-step tiles (weights only,
// input-independent) are converted+staged into smem BEFORE
// cudaGridDependencySynchronize — fully hidden under the predecessor k_update.
// Post-sync: all 8 A-loads issued back-to-back (one exposed L2 latency), then
// 8 x {STS-A, MMA} with A double-buffered. Arithmetic order identical to R13.
__global__ __launch_bounds__(256) void k_lvl(
    const float* __restrict__ Wiouh, const float* __restrict__ Wfh, int j0, int P)
{
    extern __shared__ uint32_t sm[];
    uint32_t (*Bs)[32][72] = (uint32_t (*)[32][72])sm;              // [8][32][72]
    uint32_t (*As)[32][36] = (uint32_t (*)[32][36])(sm + 8 * 32 * 72);  // [2][32][36]

    const int tid = threadIdx.x;
    const int n0 = blockIdx.x * 64;
    const int mt = blockIdx.y >> 1;
    const int s  = blockIdx.y & 1;
    const int t  = blockIdx.z;
    const int kbase = s * 256;
    const int m0 = mt * 32;

    const int arow = tid >> 3;
    const int acol = (tid & 7) << 2;
    const int brow = tid >> 4;
    const int bc4  = (tid & 15) << 2;

    const float* Bsrc; int bld;
    if (n0 < NIOU) { Bsrc = Wiouh + n0;          bld = NIOU; }
    else           { Bsrc = Wfh + (n0 - NIOU);   bld = MEMD; }
    Bsrc += (size_t)kbase * bld;

    // ---- PDL prologue: stage the ENTIRE B operand (weights only) ----
#pragma unroll
    for (int it = 0; it < 8; it++) {
        int k0 = it * 32;
        *(uint4*)&Bs[it][brow][bc4]      = cvt4(ld4(Bsrc + (size_t)(k0 + brow) * bld + bc4));
        *(uint4*)&Bs[it][brow + 16][bc4] = cvt4(ld4(Bsrc + (size_t)(k0 + brow + 16) * bld + bc4));
    }

    cudaGridDependencySynchronize();

    const int gm = m0 + arow;
    const bool avalid = (gm < P);
    const float* aptr = g_h + (size_t)(t * NPAD + j0 + (avalid ? gm : 0)) * MEMD + kbase + acol;

    // Issue all 8 A loads back-to-back (MLP=8: one exposed L2 latency).
    float4 aval[8];
#pragma unroll
    for (int it = 0; it < 8; it++)
        aval[it] = avalid ? ld4(aptr + it * 32) : make_float4(0.f, 0.f, 0.f, 0.f);

    const int lane = tid & 31, wid = tid >> 5;
    const int wm = (wid & 1) * 16, wn = (wid >> 1) * 16;
    const int g = lane >> 2, tg = lane & 3;

    float acc[2][4] = {};

    *(uint4*)&As[0][arow][acol] = cvt4(aval[0]);
    __syncthreads();   // also makes pre-sync Bs visible to all warps

    int cur = 0;
#pragma unroll
    for (int it = 0; it < 8; it++) {
        if (it < 7)
            *(uint4*)&As[cur ^ 1][arow][acol] = cvt4(aval[it + 1]);
#pragma unroll
        for (int kk = 0; kk < 32; kk += 8) {
            uint32_t af[4], bf[2][2];
            af[0] = As[cur][wm + g][kk + tg];
            af[1] = As[cur][wm + g + 8][kk + tg];
            af[2] = As[cur][wm + g][kk + tg + 4];
            af[3] = As[cur][wm + g + 8][kk + tg + 4];
#pragma unroll
            for (int j = 0; j < 2; j++) {
                int bc = wn + j * 8 + g;
                bf[j][0] = Bs[it][kk + tg][bc];
                bf[j][1] = Bs[it][kk + tg + 4][bc];
            }
            mma_tf32(acc[0], af, bf[0]);
            mma_tf32(acc[1], af, bf[1]);
        }
        if (it < 7) {
            __syncthreads();
            cur ^= 1;
        }
    }

    float* zout = s ? g_zyB : g_zyA;
#pragma unroll
    for (int j = 0; j < 2; j++) {
        int colin = wn + j * 8 + 2 * tg;
#pragma unroll
        for (int r = 0; r < 2; r++) {
            int mrow = m0 + wm + g + r * 8;
            if (mrow < P) {
                float2 v = make_float2(acc[j][2 * r], acc[j][2 * r + 1]);
                *(float2*)(zout + (size_t)(t * NPAD + j0 + mrow) * NCOMB + n0 + colin) = v;
            }
        }
    }
}

// Per-node gate math for one level (PDL: indices + biases loaded pre-sync).
__global__ __launch_bounds__(128) void k_update(
    const int* __restrict__ lch, const int* __restrict__ rch,
    const float* __restrict__ biouh, const float* __restrict__ bfh, int j0)
{
    const int t = blockIdx.y;
    const int j = j0 + blockIdx.x;
    const int* ch = (t ? rch : lch) + j * 4;
    const int d = threadIdx.x << 2;

    // ---- PDL prologue: kernel inputs only ----
    const int c0i = ch[0], c1i = ch[1], c2i = ch[2], c3i = ch[3];
    float4 Bi = ld4(biouh + d), Bo = ld4(biouh + 512 + d), Bu = ld4(biouh + 1024 + d), Bf = ld4(bfh + d);

    cudaGridDependencySynchronize();

    const int chl[4] = {c0i, c1i, c2i, c3i};
    const float* x = g_xiouf + (size_t)(t * NNODE + j) * NCOMB;

    float4 Zi = make_float4(0.f, 0.f, 0.f, 0.f);
    float4 Zo = Zi, Zu = Zi;
    float4 Y[4], Cc[4];
#pragma unroll
    for (int q = 0; q < 4; q++) {
        int c = chl[q];
        if (c < NNODE) {
            size_t zoff = (size_t)(t * NPAD + c) * NCOMB;
            const float* zA = g_zyA + zoff;
            const float* zB = g_zyB + zoff;
            Zi = f4add(Zi, f4add(ld4(zA + d),        ld4(zB + d)));
            Zo = f4add(Zo, f4add(ld4(zA + 512 + d),  ld4(zB + 512 + d)));
            Zu = f4add(Zu, f4add(ld4(zA + 1024 + d), ld4(zB + 1024 + d)));
            Y[q]  = f4add(ld4(zA + 1536 + d), ld4(zB + 1536 + d));
            Cc[q] = ld4(g_c + (size_t)(t * NPAD + c) * MEMD + d);
        } else {
            Y[q] = Cc[q] = make_float4(0.f, 0.f, 0.f, 0.f);
        }
    }

    float4 Xi = ld4(x + d), Xo = ld4(x + 512 + d), Xu = ld4(x + 1024 + d), Xf = ld4(x + 1536 + d);

    float4 Oc, Oh;
#define DO(C) { \
    float ig = sigm(Xi.C + Zi.C + Bi.C); \
    float og = sigm(Xo.C + Zo.C + Bo.C); \
    float ug = tanhf(Xu.C + Zu.C + Bu.C); \
    float fb = Xf.C + Bf.C; \
    float c  = ig * ug + sigm(Y[0].C + fb) * Cc[0].C + sigm(Y[1].C + fb) * Cc[1].C \
                       + sigm(Y[2].C + fb) * Cc[2].C + sigm(Y[3].C + fb) * Cc[3].C; \
    Oc.C = c; Oh.C = og * tanhf(c); }
    DO(x) DO(y) DO(z) DO(w)
#undef DO

    *(float4*)(g_c + (size_t)(t * NPAD + j) * MEMD + d) = Oc;
    *(float4*)(g_h + (size_t)(t * NPAD + j) * MEMD + d) = Oh;
}

// Fused root-update + head part 1. Each of 16 blocks recomputes the 64-dim slice
// of the root cell state it needs (redundant x2 across blocks; trivial cost),
// then forms vec = [lc*rc | |lc-rc|] slice and partial hid pre-activations.
__global__ __launch_bounds__(512) void k_head1f(
    const int* __restrict__ lch, const int* __restrict__ rch,
    const float* __restrict__ biouh, const float* __restrict__ bfh,
    const float* __restrict__ Wh)
{
    __shared__ float sh_c[2][64];
    __shared__ float vec_s[64];
    const int b = blockIdx.x, tid = threadIdx.x;
    const int s0 = (b & 7) * 64;

    cudaGridDependencySynchronize();

    if (tid < 128) {
        int t = tid >> 6;
        int i = tid & 63;
        int dd = s0 + i;
        const int* ch = (t ? rch : lch) + 511 * 4;
        const float* x = g_xiouf + (size_t)(t * NNODE + 511) * NCOMB;
        float zi = 0.f, zu = 0.f;
        float y[4], cc[4];
#pragma unroll
        for (int q = 0; q < 4; q++) {
            int c = ch[q];  // root children are real nodes
            size_t zoff = (size_t)(t * NPAD + c) * NCOMB;
            zi += g_zyA[zoff + dd] + g_zyB[zoff + dd];
            zu += g_zyA[zoff + 1024 + dd] + g_zyB[zoff + 1024 + dd];
            y[q]  = g_zyA[zoff + 1536 + dd] + g_zyB[zoff + 1536 + dd];
            cc[q] = g_c[(size_t)(t * NPAD + c) * MEMD + dd];
        }
        float ig = sigm(x[dd] + zi + biouh[dd]);
        float ug = tanhf(x[1024 + dd] + zu + biouh[1024 + dd]);
        float fb = x[1536 + dd] + bfh[dd];
        float cval = ig * ug + sigm(y[0] + fb) * cc[0] + sigm(y[1] + fb) * cc[1]
                             + sigm(y[2] + fb) * cc[2] + sigm(y[3] + fb) * cc[3];
        sh_c[t][i] = cval;
    }
    __syncthreads();
    if (tid < 64) {
        float l = sh_c[0][tid], r = sh_c[1][tid];
        vec_s[tid] = (b < 8) ? l * r : fabsf(l - r);
    }
    __syncthreads();
    float acc = 0.f;
    int d0 = b * 64;
#pragma unroll 8
    for (int dd = 0; dd < 64; dd++)
        acc += vec_s[dd] * Wh[(size_t)(d0 + dd) * 512 + tid];
    g_part[b * 512 + tid] = acc;
}

// Head part 2: hid = sigmoid(.+bh); logits = hid@Wp+bp; log_softmax -> out[5]
__global__ __launch_bounds__(512) void k_head2(
    const float* __restrict__ bh, const float* __restrict__ Wp,
    const float* __restrict__ bp, float* __restrict__ out)
{
    __shared__ float hid[512];
    __shared__ float logit[5];
    const int tid = threadIdx.x;

    cudaGridDependencySynchronize();

    float a = 0.f;
#pragma unroll
    for (int b = 0; b < 16; b++) a += g_part[b * 512 + tid];
    hid[tid] = sigm(a + bh[tid]);
    __syncthreads();
    if (tid < 160) {
        int c = tid / 32, lane = tid & 31;
        float s = 0.f;
        for (int o = lane; o < 512; o += 32) s += hid[o] * Wp[o * 5 + c];
#pragma unroll
        for (int off = 16; off; off >>= 1) s += __shfl_down_sync(0xffffffffu, s, off);
        if (lane == 0) logit[c] = s + bp[c];
    }
    __syncthreads();
    if (tid == 0) {
        float m = logit[0];
#pragma unroll
        for (int c = 1; c < 5; c++) m = fmaxf(m, logit[c]);
        float se = 0.f;
#pragma unroll
        for (int c = 0; c < 5; c++) se += expf(logit[c] - m);
        float lse = m + logf(se);
#pragma unroll
        for (int c = 0; c < 5; c++) out[c] = logit[c] - lse;
    }
}

extern "C" void kernel_launch(void* const* d_in, const int* in_sizes, int n_in,
                              void* d_out, int out_size)
{
    const int*   linp  = (const int*)d_in[0];
    const int*   rinp  = (const int*)d_in[1];
    const int*   lch   = (const int*)d_in[2];
    const int*   rch   = (const int*)d_in[3];
    const float* emb   = (const float*)d_in[4];
    const float* Wioux = (const float*)d_in[5];
    const float* bioux = (const float*)d_in[6];
    const float* Wiouh = (const float*)d_in[7];
    const float* biouh = (const float*)d_in[8];
    const float* Wfx   = (const float*)d_in[9];
    const float* bfx   = (const float*)d_in[10];
    const float* Wfh   = (const float*)d_in[11];
    const float* bfh   = (const float*)d_in[12];
    const float* Wh    = (const float*)d_in[13];
    const float* bh    = (const float*)d_in[14];
    const float* Wp    = (const float*)d_in[15];
    const float* bp    = (const float*)d_in[16];
    float* out = (float*)d_out;

    cudaFuncSetAttribute(k_lvl, cudaFuncAttributeMaxDynamicSharedMemorySize, LVL_SMEM);

    // First launch: normal (its predecessor is outside our chain).
    k_pre<<<dim3(32, 32, 1), 256>>>(emb, linp, rinp, Wioux, Wfx, bioux, bfx);

    // All subsequent launches: PDL so each kernel's launch + input-only prologue
    // overlaps the predecessor's tail.
    cudaLaunchAttribute attr;
    attr.id = cudaLaunchAttributeProgrammaticStreamSerialization;
    attr.val.programmaticStreamSerializationAllowed = 1;
    cudaLaunchConfig_t cfg = {};
    cfg.attrs = &attr;
    cfg.numAttrs = 1;
    cfg.stream = 0;

    static const int j0s[5] = {0, 171, 427, 491, 507};
    static const int cnt[5] = {171, 256, 64, 16, 4};
    for (int l = 0; l < 5; l++) {
        cfg.gridDim = dim3(cnt[l], 2, 1);
        cfg.blockDim = dim3(128, 1, 1);
        cfg.dynamicSmemBytes = 0;
        cudaLaunchKernelEx(&cfg, k_update, lch, rch, biouh, bfh, j0s[l]);

        int mt = (cnt[l] + 31) / 32;
        cfg.gridDim = dim3(32, mt * 2, 2);
        cfg.blockDim = dim3(256, 1, 1);
        cfg.dynamicSmemBytes = LVL_SMEM;
        cudaLaunchKernelEx(&cfg, k_lvl, Wiouh, Wfh, j0s[l], cnt[l]);
    }

    cfg.gridDim = dim3(16, 1, 1);
    cfg.blockDim = dim3(512, 1, 1);
    cfg.dynamicSmemBytes = 0;
    cudaLaunchKernelEx(&cfg, k_head1f, lch, rch, biouh, bfh, Wh);

    cfg.gridDim = dim3(1, 1, 1);
    cfg.blockDim = dim3(512, 1, 1);
    cudaLaunchKernelEx(&cfg, k_head2, bh, Wp, bp, out);
}

// round 17
// speedup vs baseline: 1.4459x; 1.0006x over previous
#include <cuda_runtime.h>
#include <math.h>
#include <stdint.h>

#define NNODE 512
#define MEMD  512
#define NIOU  1536
#define NCOMB 2048
#define NPAD  513

// k_lvl dynamic smem: Bs[8][32][72] + As[2][32][36]
#define LVL_SMEM ((8 * 32 * 72 + 2 * 32 * 36) * 4)

// Scratch state (device globals: allocation-free rule)
__device__ float g_xiouf[2 * NNODE * NCOMB];  // [xiou(1536) | xf(512)] per node, biases included
__device__ float g_zyA[2 * NPAD * NCOMB];     // K-slice 0 partial of h @ [W_iouh | W_fh]
__device__ float g_zyB[2 * NPAD * NCOMB];     // K-slice 1 partial
__device__ float g_c[2 * NPAD * MEMD];
__device__ float g_h[2 * NPAD * MEMD];
__device__ float g_part[16 * MEMD];           // head partial sums

__device__ __forceinline__ float sigm(float x) { return 1.f / (1.f + __expf(-x)); }
__device__ __forceinline__ float4 ld4(const float* p) { return *(const float4*)p; }
__device__ __forceinline__ float4 f4add(float4 a, float4 b) {
    return make_float4(a.x + b.x, a.y + b.y, a.z + b.z, a.w + b.w);
}
__device__ __forceinline__ uint32_t to_tf32(float x) {
    uint32_t r; asm("cvt.rna.tf32.f32 %0, %1;" : "=r"(r) : "f"(x)); return r;
}
__device__ __forceinline__ uint4 cvt4(float4 v) {
    uint4 r; r.x = to_tf32(v.x); r.y = to_tf32(v.y); r.z = to_tf32(v.z); r.w = to_tf32(v.w);
    return r;
}
__device__ __forceinline__ void mma_tf32(float d[4], const uint32_t a[4], const uint32_t b[2]) {
    asm volatile(
        "mma.sync.aligned.m16n8k8.row.col.f32.tf32.tf32.f32 "
        "{%0,%1,%2,%3}, {%4,%5,%6,%7}, {%8,%9}, {%0,%1,%2,%3};"
        : "+f"(d[0]), "+f"(d[1]), "+f"(d[2]), "+f"(d[3])
        : "r"(a[0]), "r"(a[1]), "r"(a[2]), "r"(a[3]), "r"(b[0]), "r"(b[1]));
}

// Precompute tf32 GEMM: 32(M)x64(N)xK512 block tile, BK=32, 256 threads (8 warps,
// 16x16 warp tiles), double-buffered smem. As stride 36 (= 4 mod 32): conflict-free
// A-frag reads. Bs stride 72 (= 8 mod 32) for the B-frag pattern.
// C[m] = emb[tok[m]] @ [W_ioux|W_fx] + [b_ioux|b_fx]  -> g_xiouf  (m over 1024 rows)
__global__ __launch_bounds__(256) void k_pre(
    const float* __restrict__ emb, const int* __restrict__ linp, const int* __restrict__ rinp,
    const float* __restrict__ W0, const float* __restrict__ W1,
    const float* __restrict__ b0, const float* __restrict__ b1)
{
    __shared__ uint32_t As[2][32][36];
    __shared__ uint32_t Bs[2][32][72];

    const int tid = threadIdx.x;
    const int n0 = blockIdx.x * 64;
    const int m0 = blockIdx.y * 32;

    const int arow = tid >> 3;
    const int acol = (tid & 7) << 2;
    const int brow = tid >> 4;
    const int bc4  = (tid & 15) << 2;

    const float* aptr;
    {
        int gm = m0 + arow;
        int tok = (gm < NNODE) ? linp[gm] : rinp[gm - NNODE];
        aptr = emb + (size_t)tok * MEMD + acol;
    }

    const float* Bsrc; int bld; const float* bias;
    if (n0 < NIOU) { Bsrc = W0 + n0;          bld = NIOU; bias = b0 + n0; }
    else           { Bsrc = W1 + (n0 - NIOU); bld = MEMD; bias = b1 + n0 - NIOU; }

    const int lane = tid & 31, wid = tid >> 5;
    const int wm = (wid & 1) * 16, wn = (wid >> 1) * 16;
    const int g = lane >> 2, tg = lane & 3;

    float acc[2][4] = {};

    *(uint4*)&As[0][arow][acol]     = cvt4(ld4(aptr));
    *(uint4*)&Bs[0][brow][bc4]      = cvt4(ld4(Bsrc + (size_t)brow * bld + bc4));
    *(uint4*)&Bs[0][brow + 16][bc4] = cvt4(ld4(Bsrc + (size_t)(brow + 16) * bld + bc4));
    __syncthreads();

    int cur = 0;
    for (int it = 0; it < 16; it++) {
        float4 an, bn0, bn1;
        if (it < 15) {
            int k0 = (it + 1) * 32;
            an  = ld4(aptr + k0);
            bn0 = ld4(Bsrc + (size_t)(k0 + brow) * bld + bc4);
            bn1 = ld4(Bsrc + (size_t)(k0 + brow + 16) * bld + bc4);
        }
#pragma unroll
        for (int kk = 0; kk < 32; kk += 8) {
            uint32_t af[4], bf[2][2];
            af[0] = As[cur][wm + g][kk + tg];
            af[1] = As[cur][wm + g + 8][kk + tg];
            af[2] = As[cur][wm + g][kk + tg + 4];
            af[3] = As[cur][wm + g + 8][kk + tg + 4];
#pragma unroll
            for (int j = 0; j < 2; j++) {
                int bc = wn + j * 8 + g;
                bf[j][0] = Bs[cur][kk + tg][bc];
                bf[j][1] = Bs[cur][kk + tg + 4][bc];
            }
            mma_tf32(acc[0], af, bf[0]);
            mma_tf32(acc[1], af, bf[1]);
        }
        if (it < 15) {
            int nxt = cur ^ 1;
            *(uint4*)&As[nxt][arow][acol]     = cvt4(an);
            *(uint4*)&Bs[nxt][brow][bc4]      = cvt4(bn0);
            *(uint4*)&Bs[nxt][brow + 16][bc4] = cvt4(bn1);
            __syncthreads();
            cur = nxt;
        }
    }

#pragma unroll
    for (int j = 0; j < 2; j++) {
        int colin = wn + j * 8 + 2 * tg;
#pragma unroll
        for (int r = 0; r < 2; r++) {
            int mrow = m0 + wm + g + r * 8;
            float2 v = make_float2(acc[j][2 * r], acc[j][2 * r + 1]);
            v.x += bias[colin]; v.y += bias[colin + 1];
            *(float2*)(g_xiouf + (size_t)mrow * NCOMB + n0 + colin) = v;
        }
    }
}

// Leaf update: all 384 leaves per tree (j in [0,384)) have only pad children.
// c = sigm(Xi+Bi)*tanh(Xu+Bu); h = sigm(Xo+Bo)*tanh(c). Depends only on k_pre.
__global__ __launch_bounds__(128) void k_leaf(
    const float* __restrict__ biouh)
{
    const int t = blockIdx.y;
    const int j = blockIdx.x;
    const int d = threadIdx.x << 2;

    // ---- PDL prologue: kernel inputs only ----
    float4 Bi = ld4(biouh + d), Bo = ld4(biouh + 512 + d), Bu = ld4(biouh + 1024 + d);

    cudaGridDependencySynchronize();

    const float* x = g_xiouf + (size_t)(t * NNODE + j) * NCOMB;
    float4 Xi = ld4(x + d), Xo = ld4(x + 512 + d), Xu = ld4(x + 1024 + d);

    float4 Oc, Oh;
#define DOL(C) { \
    float ig = sigm(Xi.C + Bi.C); \
    float og = sigm(Xo.C + Bo.C); \
    float ug = tanhf(Xu.C + Bu.C); \
    float c  = ig * ug; \
    Oc.C = c; Oh.C = og * tanhf(c); }
    DOL(x) DOL(y) DOL(z) DOL(w)
#undef DOL

    *(float4*)(g_c + (size_t)(t * NPAD + j) * MEMD + d) = Oc;
    *(float4*)(g_h + (size_t)(t * NPAD + j) * MEMD + d) = Oh;
}

// Level GEMM, split-K=2, full-B PDL prologue (unchanged from R14 winner).
__global__ __launch_bounds__(256) void k_lvl(
    const float* __restrict__ Wiouh, const float* __restrict__ Wfh, int j0, int P)
{
    extern __shared__ uint32_t sm[];
    uint32_t (*Bs)[32][72] = (uint32_t (*)[32][72])sm;                  // [8][32][72]
    uint32_t (*As)[32][36] = (uint32_t (*)[32][36])(sm + 8 * 32 * 72);  // [2][32][36]

    const int tid = threadIdx.x;
    const int n0 = blockIdx.x * 64;
    const int mt = blockIdx.y >> 1;
    const int s  = blockIdx.y & 1;
    const int t  = blockIdx.z;
    const int kbase = s * 256;
    const int m0 = mt * 32;

    const int arow = tid >> 3;
    const int acol = (tid & 7) << 2;
    const int brow = tid >> 4;
    const int bc4  = (tid & 15) << 2;

    const float* Bsrc; int bld;
    if (n0 < NIOU) { Bsrc = Wiouh + n0;          bld = NIOU; }
    else           { Bsrc = Wfh + (n0 - NIOU);   bld = MEMD; }
    Bsrc += (size_t)kbase * bld;

    // ---- PDL prologue: stage the ENTIRE B operand (weights only) ----
#pragma unroll
    for (int it = 0; it < 8; it++) {
        int k0 = it * 32;
        *(uint4*)&Bs[it][brow][bc4]      = cvt4(ld4(Bsrc + (size_t)(k0 + brow) * bld + bc4));
        *(uint4*)&Bs[it][brow + 16][bc4] = cvt4(ld4(Bsrc + (size_t)(k0 + brow + 16) * bld + bc4));
    }

    cudaGridDependencySynchronize();

    const int gm = m0 + arow;
    const bool avalid = (gm < P);
    const float* aptr = g_h + (size_t)(t * NPAD + j0 + (avalid ? gm : 0)) * MEMD + kbase + acol;

    // Issue all 8 A loads back-to-back (MLP=8: one exposed L2 latency).
    float4 aval[8];
#pragma unroll
    for (int it = 0; it < 8; it++)
        aval[it] = avalid ? ld4(aptr + it * 32) : make_float4(0.f, 0.f, 0.f, 0.f);

    const int lane = tid & 31, wid = tid >> 5;
    const int wm = (wid & 1) * 16, wn = (wid >> 1) * 16;
    const int g = lane >> 2, tg = lane & 3;

    float acc[2][4] = {};

    *(uint4*)&As[0][arow][acol] = cvt4(aval[0]);
    __syncthreads();   // also makes pre-sync Bs visible to all warps

    int cur = 0;
#pragma unroll
    for (int it = 0; it < 8; it++) {
        if (it < 7)
            *(uint4*)&As[cur ^ 1][arow][acol] = cvt4(aval[it + 1]);
#pragma unroll
        for (int kk = 0; kk < 32; kk += 8) {
            uint32_t af[4], bf[2][2];
            af[0] = As[cur][wm + g][kk + tg];
            af[1] = As[cur][wm + g + 8][kk + tg];
            af[2] = As[cur][wm + g][kk + tg + 4];
            af[3] = As[cur][wm + g + 8][kk + tg + 4];
#pragma unroll
            for (int j = 0; j < 2; j++) {
                int bc = wn + j * 8 + g;
                bf[j][0] = Bs[it][kk + tg][bc];
                bf[j][1] = Bs[it][kk + tg + 4][bc];
            }
            mma_tf32(acc[0], af, bf[0]);
            mma_tf32(acc[1], af, bf[1]);
        }
        if (it < 7) {
            __syncthreads();
            cur ^= 1;
        }
    }

    float* zout = s ? g_zyB : g_zyA;
#pragma unroll
    for (int j = 0; j < 2; j++) {
        int colin = wn + j * 8 + 2 * tg;
#pragma unroll
        for (int r = 0; r < 2; r++) {
            int mrow = m0 + wm + g + r * 8;
            if (mrow < P) {
                float2 v = make_float2(acc[j][2 * r], acc[j][2 * r + 1]);
                *(float2*)(zout + (size_t)(t * NPAD + j0 + mrow) * NCOMB + n0 + colin) = v;
            }
        }
    }
}

// Per-node gate math for internal nodes (PDL: indices + biases loaded pre-sync).
// All children real (internal nodes of a complete tree); guard kept for safety.
__global__ __launch_bounds__(128) void k_update(
    const int* __restrict__ lch, const int* __restrict__ rch,
    const float* __restrict__ biouh, const float* __restrict__ bfh, int j0)
{
    const int t = blockIdx.y;
    const int j = j0 + blockIdx.x;
    const int* ch = (t ? rch : lch) + j * 4;
    const int d = threadIdx.x << 2;

    // ---- PDL prologue: kernel inputs only ----
    const int c0i = ch[0], c1i = ch[1], c2i = ch[2], c3i = ch[3];
    float4 Bi = ld4(biouh + d), Bo = ld4(biouh + 512 + d), Bu = ld4(biouh + 1024 + d), Bf = ld4(bfh + d);

    cudaGridDependencySynchronize();

    const int chl[4] = {c0i, c1i, c2i, c3i};
    const float* x = g_xiouf + (size_t)(t * NNODE + j) * NCOMB;

    float4 Zi = make_float4(0.f, 0.f, 0.f, 0.f);
    float4 Zo = Zi, Zu = Zi;
    float4 Y[4], Cc[4];
#pragma unroll
    for (int q = 0; q < 4; q++) {
        int c = chl[q];
        if (c < NNODE) {
            size_t zoff = (size_t)(t * NPAD + c) * NCOMB;
            const float* zA = g_zyA + zoff;
            const float* zB = g_zyB + zoff;
            Zi = f4add(Zi, f4add(ld4(zA + d),        ld4(zB + d)));
            Zo = f4add(Zo, f4add(ld4(zA + 512 + d),  ld4(zB + 512 + d)));
            Zu = f4add(Zu, f4add(ld4(zA + 1024 + d), ld4(zB + 1024 + d)));
            Y[q]  = f4add(ld4(zA + 1536 + d), ld4(zB + 1536 + d));
            Cc[q] = ld4(g_c + (size_t)(t * NPAD + c) * MEMD + d);
        } else {
            Y[q] = Cc[q] = make_float4(0.f, 0.f, 0.f, 0.f);
        }
    }

    float4 Xi = ld4(x + d), Xo = ld4(x + 512 + d), Xu = ld4(x + 1024 + d), Xf = ld4(x + 1536 + d);

    float4 Oc, Oh;
#define DO(C) { \
    float ig = sigm(Xi.C + Zi.C + Bi.C); \
    float og = sigm(Xo.C + Zo.C + Bo.C); \
    float ug = tanhf(Xu.C + Zu.C + Bu.C); \
    float fb = Xf.C + Bf.C; \
    float c  = ig * ug + sigm(Y[0].C + fb) * Cc[0].C + sigm(Y[1].C + fb) * Cc[1].C \
                       + sigm(Y[2].C + fb) * Cc[2].C + sigm(Y[3].C + fb) * Cc[3].C; \
    Oc.C = c; Oh.C = og * tanhf(c); }
    DO(x) DO(y) DO(z) DO(w)
#undef DO

    *(float4*)(g_c + (size_t)(t * NPAD + j) * MEMD + d) = Oc;
    *(float4*)(g_h + (size_t)(t * NPAD + j) * MEMD + d) = Oh;
}

// Fused root-update + head part 1 (unchanged from R14 winner).
__global__ __launch_bounds__(512) void k_head1f(
    const int* __restrict__ lch, const int* __restrict__ rch,
    const float* __restrict__ biouh, const float* __restrict__ bfh,
    const float* __restrict__ Wh)
{
    __shared__ float sh_c[2][64];
    __shared__ float vec_s[64];
    const int b = blockIdx.x, tid = threadIdx.x;
    const int s0 = (b & 7) * 64;

    cudaGridDependencySynchronize();

    if (tid < 128) {
        int t = tid >> 6;
        int i = tid & 63;
        int dd = s0 + i;
        const int* ch = (t ? rch : lch) + 511 * 4;
        const float* x = g_xiouf + (size_t)(t * NNODE + 511) * NCOMB;
        float zi = 0.f, zu = 0.f;
        float y[4], cc[4];
#pragma unroll
        for (int q = 0; q < 4; q++) {
            int c = ch[q];  // root children are real nodes
            size_t zoff = (size_t)(t * NPAD + c) * NCOMB;
            zi += g_zyA[zoff + dd] + g_zyB[zoff + dd];
            zu += g_zyA[zoff + 1024 + dd] + g_zyB[zoff + 1024 + dd];
            y[q]  = g_zyA[zoff + 1536 + dd] + g_zyB[zoff + 1536 + dd];
            cc[q] = g_c[(size_t)(t * NPAD + c) * MEMD + dd];
        }
        float ig = sigm(x[dd] + zi + biouh[dd]);
        float ug = tanhf(x[1024 + dd] + zu + biouh[1024 + dd]);
        float fb = x[1536 + dd] + bfh[dd];
        float cval = ig * ug + sigm(y[0] + fb) * cc[0] + sigm(y[1] + fb) * cc[1]
                             + sigm(y[2] + fb) * cc[2] + sigm(y[3] + fb) * cc[3];
        sh_c[t][i] = cval;
    }
    __syncthreads();
    if (tid < 64) {
        float l = sh_c[0][tid], r = sh_c[1][tid];
        vec_s[tid] = (b < 8) ? l * r : fabsf(l - r);
    }
    __syncthreads();
    float acc = 0.f;
    int d0 = b * 64;
#pragma unroll 8
    for (int dd = 0; dd < 64; dd++)
        acc += vec_s[dd] * Wh[(size_t)(d0 + dd) * 512 + tid];
    g_part[b * 512 + tid] = acc;
}

// Head part 2: hid = sigmoid(.+bh); logits = hid@Wp+bp; log_softmax -> out[5]
__global__ __launch_bounds__(512) void k_head2(
    const float* __restrict__ bh, const float* __restrict__ Wp,
    const float* __restrict__ bp, float* __restrict__ out)
{
    __shared__ float hid[512];
    __shared__ float logit[5];
    const int tid = threadIdx.x;

    cudaGridDependencySynchronize();

    float a = 0.f;
#pragma unroll
    for (int b = 0; b < 16; b++) a += g_part[b * 512 + tid];
    hid[tid] = sigm(a + bh[tid]);
    __syncthreads();
    if (tid < 160) {
        int c = tid / 32, lane = tid & 31;
        float s = 0.f;
        for (int o = lane; o < 512; o += 32) s += hid[o] * Wp[o * 5 + c];
#pragma unroll
        for (int off = 16; off; off >>= 1) s += __shfl_down_sync(0xffffffffu, s, off);
        if (lane == 0) logit[c] = s + bp[c];
    }
    __syncthreads();
    if (tid == 0) {
        float m = logit[0];
#pragma unroll
        for (int c = 1; c < 5; c++) m = fmaxf(m, logit[c]);
        float se = 0.f;
#pragma unroll
        for (int c = 0; c < 5; c++) se += expf(logit[c] - m);
        float lse = m + logf(se);
#pragma unroll
        for (int c = 0; c < 5; c++) out[c] = logit[c] - lse;
    }
}

extern "C" void kernel_launch(void* const* d_in, const int* in_sizes, int n_in,
                              void* d_out, int out_size)
{
    const int*   linp  = (const int*)d_in[0];
    const int*   rinp  = (const int*)d_in[1];
    const int*   lch   = (const int*)d_in[2];
    const int*   rch   = (const int*)d_in[3];
    const float* emb   = (const float*)d_in[4];
    const float* Wioux = (const float*)d_in[5];
    const float* bioux = (const float*)d_in[6];
    const float* Wiouh = (const float*)d_in[7];
    const float* biouh = (const float*)d_in[8];
    const float* Wfx   = (const float*)d_in[9];
    const float* bfx   = (const float*)d_in[10];
    const float* Wfh   = (const float*)d_in[11];
    const float* bfh   = (const float*)d_in[12];
    const float* Wh    = (const float*)d_in[13];
    const float* bh    = (const float*)d_in[14];
    const float* Wp    = (const float*)d_in[15];
    const float* bp    = (const float*)d_in[16];
    float* out = (float*)d_out;

    cudaFuncSetAttribute(k_lvl, cudaFuncAttributeMaxDynamicSharedMemorySize, LVL_SMEM);

    // First launch: normal (its predecessor is outside our chain).
    k_pre<<<dim3(32, 32, 1), 256>>>(emb, linp, rinp, Wioux, Wfx, bioux, bfx);

    // All subsequent launches: PDL.
    cudaLaunchAttribute attr;
    attr.id = cudaLaunchAttributeProgrammaticStreamSerialization;
    attr.val.programmaticStreamSerializationAllowed = 1;
    cudaLaunchConfig_t cfg = {};
    cfg.attrs = &attr;
    cfg.numAttrs = 1;
    cfg.stream = 0;

    // 1) All 384x2 leaf updates at once (depend only on k_pre).
    cfg.gridDim = dim3(384, 2, 1);
    cfg.blockDim = dim3(128, 1, 1);
    cfg.dynamicSmemBytes = 0;
    cudaLaunchKernelEx(&cfg, k_leaf, biouh);

    // 2) z for ALL leaves in one merged GEMM (M=384 per tree).
    cfg.gridDim = dim3(32, ((384 + 31) / 32) * 2, 2);
    cfg.blockDim = dim3(256, 1, 1);
    cfg.dynamicSmemBytes = LVL_SMEM;
    cudaLaunchKernelEx(&cfg, k_lvl, Wiouh, Wfh, 0, 384);

    // 3) Internal-node chain: update + z per internal level.
    static const int j0s[4] = {384, 427, 491, 507};
    static const int cnt[4] = {43, 64, 16, 4};
    for (int l = 0; l < 4; l++) {
        cfg.gridDim = dim3(cnt[l], 2, 1);
        cfg.blockDim = dim3(128, 1, 1);
        cfg.dynamicSmemBytes = 0;
        cudaLaunchKernelEx(&cfg, k_update, lch, rch, biouh, bfh, j0s[l]);

        int mt = (cnt[l] + 31) / 32;
        cfg.gridDim = dim3(32, mt * 2, 2);
        cfg.blockDim = dim3(256, 1, 1);
        cfg.dynamicSmemBytes = LVL_SMEM;
        cudaLaunchKernelEx(&cfg, k_lvl, Wiouh, Wfh, j0s[l], cnt[l]);
    }

    cfg.gridDim = dim3(16, 1, 1);
    cfg.blockDim = dim3(512, 1, 1);
    cfg.dynamicSmemBytes = 0;
    cudaLaunchKernelEx(&cfg, k_head1f, lch, rch, biouh, bfh, Wh);

    cfg.gridDim = dim3(1, 1, 1);
    cfg.blockDim = dim3(512, 1, 1);
    cudaLaunchKernelEx(&cfg, k_head2, bh, Wp, bp, out);
}